// round 8
// baseline (speedup 1.0000x reference)
#include <cuda_runtime.h>
#include <math.h>

#define SB 32
#define SH 2048
#define ST 39
#define SV 8000
#define SE 50

typedef unsigned long long u64;

__device__ __forceinline__ u64 dup2(float v){
    u64 r; asm("mov.b64 %0, {%1,%1};" : "=l"(r) : "f"(v)); return r;
}
__device__ __forceinline__ u64 ffma2(u64 a, u64 b, u64 c){
    u64 d; asm("fma.rn.f32x2 %0, %1, %2, %3;" : "=l"(d) : "l"(a), "l"(b), "l"(c)); return d;
}
__device__ __forceinline__ void upk(u64 a, float& lo, float& hi){
    asm("mov.b64 {%0,%1}, %2;" : "=f"(lo), "=f"(hi) : "l"(a));
}
__device__ __forceinline__ float sigf(float x){ return 1.0f/(1.0f + expf(-x)); }

// ---- device scratch ----
// state layout [k][b]: idx = k*32 + b
__device__ __align__(16) float d_lWT [(size_t)SH*8192];   // lWhh^T, LSTM-permuted rows
__device__ __align__(16) float d_ghWT[(size_t)SH*6144];   // gWhh^T
__device__ __align__(16) float d_giWT[(size_t)SH*6144];   // gWih^T, GRU-permuted rows
__device__ __align__(16) float d_linWT[(size_t)SH*SV];    // linW^T
__device__ __align__(16) float d_Xg[(size_t)ST*8192*SB];
__device__ __align__(16) float d_h[2][SH*SB];
__device__ __align__(16) float d_c[SH*SB];
__device__ __align__(16) float d_hg[2][SH*SB];
__device__ __align__(16) float d_pgh[2][6144*SB];
__device__ __align__(16) float d_pacc[2][6144*SB];
__device__ __align__(16) float d_hgAll[(size_t)ST*SH*SB];

__global__ void setup_kernel(const float* __restrict__ feat){
    int i = blockIdx.x*blockDim.x + threadIdx.x;   // 65536
    int k = i >> 5, b = i & 31;
    float v = feat[b*SH + k];
    d_h[0][i] = v; d_c[i] = v; d_hg[0][i] = v;
}

// generic 32x32 transpose with output-row permutation
// mode 0: identity; 1: LSTM (16-col x 4-gate blocks); 2: GRU (32-col x 3-gate blocks)
__global__ void transpose_kernel(const float* __restrict__ in, float* __restrict__ out,
                                 int R, int mode){
    __shared__ float tile[32][33];
    int rb = blockIdx.x*32, kb = blockIdx.y*32;
    int tx = threadIdx.x, ty = threadIdx.y;   // 32 x 8
    #pragma unroll
    for (int i = 0; i < 4; i++)
        tile[ty + i*8][tx] = in[(size_t)(rb + ty + i*8)*SH + kb + tx];
    __syncthreads();
    int r = rb + tx;
    int p;
    if (mode == 0) p = r;
    else if (mode == 1) p = ((r & 2047) >> 4)*64 + (r >> 11)*16 + (r & 15);
    else { int g = r/2048, j = r%2048; p = (j>>5)*96 + g*32 + (j&31); }
    #pragma unroll
    for (int i = 0; i < 4; i++)
        out[(size_t)(kb + ty + i*8)*R + p] = tile[tx][ty + i*8];
}

__global__ void xg_kernel(const int* __restrict__ captions, const float* __restrict__ emb,
                          const float* __restrict__ Wih, const float* __restrict__ bih,
                          const float* __restrict__ bhh){
    __shared__ float embS[SE*SB];
    int t = blockIdx.x, jc = blockIdx.y, tid = threadIdx.x;
    for (int i = tid; i < SB*SE; i += 256){
        int b = i / SE, e = i % SE;
        int cap = captions[b*40 + t];
        embS[e*SB + b] = emb[(size_t)cap*SE + e];
    }
    __syncthreads();
    int lane = tid & 31, wid = tid >> 5;
    for (int j = jc*1024 + wid; j < jc*1024 + 1024; j += 8){
        float acc = bih[j] + bhh[j];
        const float* wr = Wih + (size_t)j*SE;
        #pragma unroll
        for (int e = 0; e < SE; e++) acc = fmaf(wr[e], embS[e*SB + lane], acc);
        d_Xg[((size_t)t*8192 + j)*SB + lane] = acc;
    }
}

// ======================================================================
// stepA: blocks 0..127   : LSTM, 64 permuted rows (16 cols x 4 gates), full K,
//                          fused LSTM elementwise epilogue.
//        blocks 128..319 : GRU hidden term, 64 rows, K split in 2 halves -> d_pgh.
// 128 threads, thread tile 16 rows x 1 batch. Double-buffered smem staging.
// ======================================================================
__global__ void __launch_bounds__(128) stepA_kernel(const float* __restrict__ lWT,
        const float* __restrict__ ghWT, int t){
    __shared__ float wb[2][32*64];
    __shared__ float sb[2][32*32];
    int tid = threadIdx.x, lane = tid & 31, w = tid >> 5;
    int rp = t & 1, wp = rp ^ 1;
    bool isL = (blockIdx.x < 128);
    const float* WT; const float* S;
    int p0, Rtot, k0, nch, kh = 0, rg = 0;
    if (isL){
        WT = lWT; S = d_h[rp]; p0 = blockIdx.x*64; Rtot = 8192; k0 = 0; nch = 64;
    } else {
        int gi = blockIdx.x - 128;
        kh = gi / 96; rg = gi % 96;
        WT = ghWT; S = d_hg[rp]; p0 = rg*64; Rtot = 6144; k0 = kh*1024; nch = 32;
    }
    int r0 = w*16;
    int wk = tid >> 4, wpos = tid & 15;
    const float4* Sf4 = (const float4*)(S) + k0*8;
    float4 wreg[4], sreg[2];
    {
        #pragma unroll
        for (int it = 0; it < 4; it++)
            wreg[it] = *(const float4*)(WT + (size_t)(k0 + wk + it*8)*Rtot + p0 + wpos*4);
        sreg[0] = Sf4[tid*2]; sreg[1] = Sf4[tid*2 + 1];
        #pragma unroll
        for (int it = 0; it < 4; it++)
            *(float4*)(wb[0] + (wk + it*8)*64 + wpos*4) = wreg[it];
        ((float4*)sb[0])[tid*2] = sreg[0];
        ((float4*)sb[0])[tid*2+1] = sreg[1];
    }
    __syncthreads();

    u64 acc[8] = {0,0,0,0,0,0,0,0};
    #pragma unroll 1
    for (int c = 0; c < nch; c++){
        int cur = c & 1;
        if (c + 1 < nch){
            int kb = k0 + (c+1)*32;
            #pragma unroll
            for (int it = 0; it < 4; it++)
                wreg[it] = *(const float4*)(WT + (size_t)(kb + wk + it*8)*Rtot + p0 + wpos*4);
            sreg[0] = Sf4[(c+1)*256 + tid*2];
            sreg[1] = Sf4[(c+1)*256 + tid*2 + 1];
        }
        const float* wc = wb[cur];
        const float* sc = sb[cur];
        #pragma unroll
        for (int kk = 0; kk < 32; kk++){
            u64 sd = dup2(sc[kk*32 + lane]);
            const ulonglong2* wv = (const ulonglong2*)(wc + kk*64 + r0);
            ulonglong2 a0 = wv[0], a1 = wv[1], a2 = wv[2], a3 = wv[3];
            acc[0] = ffma2(a0.x, sd, acc[0]);
            acc[1] = ffma2(a0.y, sd, acc[1]);
            acc[2] = ffma2(a1.x, sd, acc[2]);
            acc[3] = ffma2(a1.y, sd, acc[3]);
            acc[4] = ffma2(a2.x, sd, acc[4]);
            acc[5] = ffma2(a2.y, sd, acc[5]);
            acc[6] = ffma2(a3.x, sd, acc[6]);
            acc[7] = ffma2(a3.y, sd, acc[7]);
        }
        if (c + 1 < nch){
            int nxt = cur ^ 1;
            #pragma unroll
            for (int it = 0; it < 4; it++)
                *(float4*)(wb[nxt] + (wk + it*8)*64 + wpos*4) = wreg[it];
            ((float4*)sb[nxt])[tid*2] = sreg[0];
            ((float4*)sb[nxt])[tid*2+1] = sreg[1];
        }
        __syncthreads();
    }

    if (isL){
        float* ex = wb[0];   // 64x32 floats; last compute read wb[1] (nch even)
        #pragma unroll
        for (int i = 0; i < 8; i++){
            float lo, hi; upk(acc[i], lo, hi);
            int r = r0 + 2*i;
            ex[r*32 + lane] = lo;
            ex[(r+1)*32 + lane] = hi;
        }
        __syncthreads();
        int j0 = blockIdx.x*16;
        size_t xb = (size_t)t*8192*SB;
        #pragma unroll
        for (int it = 0; it < 4; it++){
            int id = tid + it*128;
            int jj = id >> 5, b = id & 31;
            int j = j0 + jj;
            float gi_ = ex[(     jj)*32 + b] + d_Xg[xb + (size_t)(         j)*SB + b];
            float gf_ = ex[(16 + jj)*32 + b] + d_Xg[xb + (size_t)(SH     + j)*SB + b];
            float gg_ = ex[(32 + jj)*32 + b] + d_Xg[xb + (size_t)(2*SH   + j)*SB + b];
            float go_ = ex[(48 + jj)*32 + b] + d_Xg[xb + (size_t)(3*SH   + j)*SB + b];
            float cold = d_c[j*SB + b];
            float cn = sigf(gf_)*cold + sigf(gi_)*tanhf(gg_);
            d_c[j*SB + b] = cn;
            d_h[wp][j*SB + b] = sigf(go_)*tanhf(cn);
        }
    } else {
        #pragma unroll
        for (int i = 0; i < 8; i++){
            float lo, hi; upk(acc[i], lo, hi);
            int r = rg*64 + r0 + 2*i;
            d_pgh[kh][r*SB + lane]     = lo;
            d_pgh[kh][(r+1)*SB + lane] = hi;
        }
    }
}

// ======================================================================
// stepB: 128 blocks = 64 col-groups x 2 K-halves. 96 permuted rows
// (32 cols x 3 gates), 192 threads, state = d_c, raw partials -> d_pacc.
// ======================================================================
__global__ void __launch_bounds__(192) stepB_kernel(const float* __restrict__ giWT, int t){
    __shared__ float wb[2][32*96];
    __shared__ float sb[2][32*32];
    int tid = threadIdx.x, lane = tid & 31, w = tid >> 5;
    int kh = blockIdx.x >> 6, cg = blockIdx.x & 63;
    int p0 = cg*96, k0 = kh*1024;
    int r0 = w*16;
    int wk = tid / 24, wpos = tid % 24;
    const float4* Sf4 = (const float4*)(d_c) + k0*8;
    float4 wreg[4], sreg[2];
    bool s2 = (tid < 64);
    {
        #pragma unroll
        for (int it = 0; it < 4; it++)
            wreg[it] = *(const float4*)(giWT + (size_t)(k0 + wk + it*8)*6144 + p0 + wpos*4);
        sreg[0] = Sf4[tid];
        if (s2) sreg[1] = Sf4[192 + tid];
        #pragma unroll
        for (int it = 0; it < 4; it++)
            *(float4*)(wb[0] + (wk + it*8)*96 + wpos*4) = wreg[it];
        ((float4*)sb[0])[tid] = sreg[0];
        if (s2) ((float4*)sb[0])[192 + tid] = sreg[1];
    }
    __syncthreads();

    u64 acc[8] = {0,0,0,0,0,0,0,0};
    #pragma unroll 1
    for (int c = 0; c < 32; c++){
        int cur = c & 1;
        if (c + 1 < 32){
            int kb = k0 + (c+1)*32;
            #pragma unroll
            for (int it = 0; it < 4; it++)
                wreg[it] = *(const float4*)(giWT + (size_t)(kb + wk + it*8)*6144 + p0 + wpos*4);
            sreg[0] = Sf4[(c+1)*256 + tid];
            if (s2) sreg[1] = Sf4[(c+1)*256 + 192 + tid];
        }
        const float* wc = wb[cur];
        const float* sc = sb[cur];
        #pragma unroll
        for (int kk = 0; kk < 32; kk++){
            u64 sd = dup2(sc[kk*32 + lane]);
            const ulonglong2* wv = (const ulonglong2*)(wc + kk*96 + r0);
            ulonglong2 a0 = wv[0], a1 = wv[1], a2 = wv[2], a3 = wv[3];
            acc[0] = ffma2(a0.x, sd, acc[0]);
            acc[1] = ffma2(a0.y, sd, acc[1]);
            acc[2] = ffma2(a1.x, sd, acc[2]);
            acc[3] = ffma2(a1.y, sd, acc[3]);
            acc[4] = ffma2(a2.x, sd, acc[4]);
            acc[5] = ffma2(a2.y, sd, acc[5]);
            acc[6] = ffma2(a3.x, sd, acc[6]);
            acc[7] = ffma2(a3.y, sd, acc[7]);
        }
        if (c + 1 < 32){
            int nxt = cur ^ 1;
            #pragma unroll
            for (int it = 0; it < 4; it++)
                *(float4*)(wb[nxt] + (wk + it*8)*96 + wpos*4) = wreg[it];
            ((float4*)sb[nxt])[tid] = sreg[0];
            if (s2) ((float4*)sb[nxt])[192 + tid] = sreg[1];
        }
        __syncthreads();
    }

    #pragma unroll
    for (int i = 0; i < 8; i++){
        float lo, hi; upk(acc[i], lo, hi);
        int r = p0 + r0 + 2*i;
        d_pacc[kh][r*SB + lane]     = lo;
        d_pacc[kh][(r+1)*SB + lane] = hi;
    }
}

// ---- eB: combine partials + GRU elementwise ----
__global__ void eB_kernel(const float* __restrict__ gbih, const float* __restrict__ gbhh, int t){
    int rp = t & 1, wp = rp ^ 1;
    int id0 = blockIdx.x*1024 + threadIdx.x;
    #pragma unroll
    for (int it = 0; it < 4; it++){
        int id = id0 + it*256;
        int j = id >> 5, b = id & 31;
        int cg = j >> 5, jj = j & 31;
        int base = (cg*96 + jj)*SB + b;
        float gi0 = d_pacc[0][base       ] + d_pacc[1][base       ] + gbih[j];
        float gi1 = d_pacc[0][base + 1024] + d_pacc[1][base + 1024] + gbih[SH   + j];
        float gi2 = d_pacc[0][base + 2048] + d_pacc[1][base + 2048] + gbih[2*SH + j];
        float gh0 = d_pgh[0][(size_t)(       j)*SB + b] + d_pgh[1][(size_t)(       j)*SB + b] + gbhh[j];
        float gh1 = d_pgh[0][(size_t)(SH   + j)*SB + b] + d_pgh[1][(size_t)(SH   + j)*SB + b] + gbhh[SH   + j];
        float gh2 = d_pgh[0][(size_t)(2*SH + j)*SB + b] + d_pgh[1][(size_t)(2*SH + j)*SB + b] + gbhh[2*SH + j];
        float r_ = sigf(gi0 + gh0);
        float z_ = sigf(gi1 + gh1);
        float n_ = tanhf(gi2 + r_*gh2);
        float hgo = d_hg[rp][j*SB + b];
        float hg = (1.0f - z_)*n_ + z_*hgo;
        d_hg[wp][j*SB + b] = hg;
        d_hgAll[(size_t)t*(SH*SB) + j*SB + b] = hg;
    }
}

// ======================================================================
// final: 63 v-blocks (128 rows) x 13 t-groups (3 timesteps). 256 threads,
// thread tile 16 rows x 3 t x 1 batch. Smem-transposed coalesced stores.
// ======================================================================
#define VP 132
__global__ void __launch_bounds__(256) final_kernel(const float* __restrict__ linWT,
        const float* __restrict__ linb, float* __restrict__ out){
    extern __shared__ float dyn[];
    float* wbB = dyn;            // 2 x 4096
    float* sbB = dyn + 8192;     // 2 x 3072
    int tid = threadIdx.x, lane = tid & 31, w = tid >> 5;
    int vb = blockIdx.x % 63, tg = blockIdx.x / 63;
    int v0 = vb*128, t0 = tg*3;
    int r0 = w*16;
    const float4* S0 = (const float4*)(d_hgAll + (size_t)(t0    )*(SH*SB));
    const float4* S1 = (const float4*)(d_hgAll + (size_t)(t0 + 1)*(SH*SB));
    const float4* S2 = (const float4*)(d_hgAll + (size_t)(t0 + 2)*(SH*SB));
    int wcol = v0 + lane*4; if (wcol > SV-4) wcol = SV-4;
    float4 wreg[4], sr0, sr1, sr2;
    {
        #pragma unroll
        for (int it = 0; it < 4; it++)
            wreg[it] = *(const float4*)(linWT + (size_t)(w + it*8)*SV + wcol);
        sr0 = S0[tid]; sr1 = S1[tid]; sr2 = S2[tid];
        #pragma unroll
        for (int it = 0; it < 4; it++)
            *(float4*)(wbB + (w + it*8)*128 + lane*4) = wreg[it];
        ((float4*)sbB)[tid] = sr0;
        ((float4*)sbB)[256 + tid] = sr1;
        ((float4*)sbB)[512 + tid] = sr2;
    }
    __syncthreads();

    u64 acc[24];
    #pragma unroll
    for (int i = 0; i < 24; i++) acc[i] = 0ull;

    #pragma unroll 1
    for (int c = 0; c < 64; c++){
        int cur = c & 1;
        if (c + 1 < 64){
            int kb = (c+1)*32;
            #pragma unroll
            for (int it = 0; it < 4; it++)
                wreg[it] = *(const float4*)(linWT + (size_t)(kb + w + it*8)*SV + wcol);
            sr0 = S0[(c+1)*256 + tid]; sr1 = S1[(c+1)*256 + tid]; sr2 = S2[(c+1)*256 + tid];
        }
        const float* wc = wbB + cur*4096;
        const float* sc = sbB + cur*3072;
        #pragma unroll
        for (int kk = 0; kk < 32; kk++){
            u64 s0 = dup2(sc[          kk*32 + lane]);
            u64 s1 = dup2(sc[1024 +    kk*32 + lane]);
            u64 s2 = dup2(sc[2048 +    kk*32 + lane]);
            const ulonglong2* wv = (const ulonglong2*)(wc + kk*128 + r0);
            #pragma unroll
            for (int q = 0; q < 4; q++){
                ulonglong2 a = wv[q];
                acc[     2*q  ] = ffma2(a.x, s0, acc[     2*q  ]);
                acc[     2*q+1] = ffma2(a.y, s0, acc[     2*q+1]);
                acc[ 8 + 2*q  ] = ffma2(a.x, s1, acc[ 8 + 2*q  ]);
                acc[ 8 + 2*q+1] = ffma2(a.y, s1, acc[ 8 + 2*q+1]);
                acc[16 + 2*q  ] = ffma2(a.x, s2, acc[16 + 2*q  ]);
                acc[16 + 2*q+1] = ffma2(a.y, s2, acc[16 + 2*q+1]);
            }
        }
        if (c + 1 < 64){
            int nxt = cur ^ 1;
            #pragma unroll
            for (int it = 0; it < 4; it++)
                *(float4*)(wbB + nxt*4096 + (w + it*8)*128 + lane*4) = wreg[it];
            ((float4*)(sbB + nxt*3072))[tid] = sr0;
            ((float4*)(sbB + nxt*3072))[256 + tid] = sr1;
            ((float4*)(sbB + nxt*3072))[512 + tid] = sr2;
        }
        __syncthreads();
    }

    // epilogue: ex[tt][b][v] with padded stride VP for coalesced stores
    float* ex = dyn;   // 3*32*VP = 12672 floats
    #pragma unroll
    for (int tt = 0; tt < 3; tt++){
        #pragma unroll
        for (int i = 0; i < 8; i++){
            float lo, hi; upk(acc[tt*8 + i], lo, hi);
            int v = r0 + 2*i;
            ex[(tt*32 + lane)*VP + v]     = lo;
            ex[(tt*32 + lane)*VP + v + 1] = hi;
        }
    }
    __syncthreads();
    #pragma unroll
    for (int it = 0; it < 12; it++){
        int seg = w + it*8;            // 96 (t,b) segments
        int tt = seg >> 5, b = seg & 31;
        int v = lane*4;
        if (v0 + v < SV){
            float4 ov = *(const float4*)(ex + (tt*32 + b)*VP + v);
            float4 lb = *(const float4*)(linb + v0 + v);
            ov.x += lb.x; ov.y += lb.y; ov.z += lb.z; ov.w += lb.w;
            *(float4*)(out + (size_t)b*(ST*SV) + (size_t)(t0 + tt)*SV + v0 + v) = ov;
        }
    }
}

extern "C" void kernel_launch(void* const* d_in, const int* in_sizes, int n_in,
                              void* d_out, int out_size){
    const float* features = (const float*)d_in[0];
    const int*   captions = (const int*)  d_in[1];
    const float* emb      = (const float*)d_in[2];
    const float* lWih     = (const float*)d_in[3];
    const float* lbih     = (const float*)d_in[4];
    const float* lWhh     = (const float*)d_in[5];
    const float* lbhh     = (const float*)d_in[6];
    const float* gWih     = (const float*)d_in[7];
    const float* gbih     = (const float*)d_in[8];
    const float* gWhh     = (const float*)d_in[9];
    const float* gbhh     = (const float*)d_in[10];
    const float* linW     = (const float*)d_in[11];
    const float* linb     = (const float*)d_in[12];
    float* out = (float*)d_out;

    static float* pLWT = nullptr; float* dummy; (void)dummy;
    cudaFuncSetAttribute(final_kernel, cudaFuncAttributeMaxDynamicSharedMemorySize, 57344);
    if (!pLWT){ cudaGetSymbolAddress((void**)&pLWT, d_lWT); }
    float *pGH, *pGI, *pLIN;
    cudaGetSymbolAddress((void**)&pGH,  d_ghWT);
    cudaGetSymbolAddress((void**)&pGI,  d_giWT);
    cudaGetSymbolAddress((void**)&pLIN, d_linWT);

    setup_kernel<<<256, 256>>>(features);
    transpose_kernel<<<dim3(256, 64), dim3(32,8)>>>(lWhh, pLWT, 8192, 1);
    transpose_kernel<<<dim3(192, 64), dim3(32,8)>>>(gWhh, pGH,  6144, 0);
    transpose_kernel<<<dim3(192, 64), dim3(32,8)>>>(gWih, pGI,  6144, 2);
    transpose_kernel<<<dim3(250, 64), dim3(32,8)>>>(linW, pLIN, 8000, 0);
    xg_kernel<<<dim3(ST, 8), 256>>>(captions, emb, lWih, lbih, lbhh);

    for (int t = 0; t < ST; t++){
        stepA_kernel<<<320, 128>>>(pLWT, pGH, t);
        stepB_kernel<<<128, 192>>>(pGI, t);
        eB_kernel<<<64, 256>>>(gbih, gbhh, t);
    }
    final_kernel<<<819, 256, 57344>>>(pLIN, linb, out);
}

// round 10
// speedup vs baseline: 2.3464x; 2.3464x over previous
#include <cuda_runtime.h>
#include <cuda_bf16.h>
#include <math.h>
#include <stdint.h>

#define SB 32
#define SH 2048
#define ST 39
#define SV 8000
#define SE 50

__device__ __forceinline__ float sigf(float x){ return 1.0f/(1.0f + expf(-x)); }

__device__ __forceinline__ uint32_t s2u(const void* p){
    uint32_t a; asm("{ .reg .u64 t; cvta.to.shared.u64 t, %1; cvt.u32.u64 %0, t; }" : "=r"(a) : "l"(p)); return a;
}
__device__ __forceinline__ void cpa(uint32_t dst, const void* src){
    asm volatile("cp.async.cg.shared.global [%0], [%1], 16;" :: "r"(dst), "l"(src));
}
#define CP_COMMIT asm volatile("cp.async.commit_group;" ::: "memory")
#define CP_WAIT1  asm volatile("cp.async.wait_group 1;" ::: "memory")
#define CP_WAIT0  asm volatile("cp.async.wait_group 0;" ::: "memory")

__device__ __forceinline__ void ldm4(uint32_t* r, uint32_t a){
    asm volatile("ldmatrix.sync.aligned.m8n8.x4.shared.b16 {%0,%1,%2,%3}, [%4];"
        : "=r"(r[0]),"=r"(r[1]),"=r"(r[2]),"=r"(r[3]) : "r"(a));
}
__device__ __forceinline__ void hmma(float* c, const uint32_t* a, const uint32_t* b){
    asm volatile("mma.sync.aligned.m16n8k16.row.col.f32.bf16.bf16.f32 "
        "{%0,%1,%2,%3}, {%4,%5,%6,%7}, {%8,%9}, {%0,%1,%2,%3};"
        : "+f"(c[0]),"+f"(c[1]),"+f"(c[2]),"+f"(c[3])
        : "r"(a[0]),"r"(a[1]),"r"(a[2]),"r"(a[3]), "r"(b[0]),"r"(b[1]));
}

// ---------------- device globals ----------------
// weights: [row][k] bf16, hi/lo split. LSTM/GRU-input rows gate-permuted.
__device__ __align__(16) __nv_bfloat16 g_wLhi[(size_t)8192*SH], g_wLlo[(size_t)8192*SH];
__device__ __align__(16) __nv_bfloat16 g_gHhi[(size_t)6144*SH], g_gHlo[(size_t)6144*SH];
__device__ __align__(16) __nv_bfloat16 g_gIhi[(size_t)6144*SH], g_gIlo[(size_t)6144*SH];
__device__ __align__(16) __nv_bfloat16 g_lnhi[(size_t)SV*SH],   g_lnlo[(size_t)SV*SH];
__device__ __align__(16) float d_Xg[(size_t)ST*4*SB*SH];     // [t][gate][b][k]
__device__ __align__(16) float d_cf[SB*SH];                  // [b][k] fp32
__device__ __align__(16) float d_hgf[2][SB*SH];              // [b][k] fp32
__device__ __align__(16) __nv_bfloat16 d_hs [2][2][SB*SH];   // [buf][hi/lo][b][k]
__device__ __align__(16) __nv_bfloat16 d_hgs[2][2][SB*SH];
__device__ __align__(16) __nv_bfloat16 d_cs [2][SB*SH];      // [hi/lo][b][k]
__device__ __align__(16) __nv_bfloat16 d_hgA[2][(size_t)ST*SB*SH]; // [hi/lo][(t*32+b)][k]
__device__ __align__(16) float d_preGH[3*SB*SH];             // [gate][b][k]

// ---------------- prep kernels ----------------
__global__ void splitw_kernel(const float2* __restrict__ src, __nv_bfloat162* __restrict__ hi,
                              __nv_bfloat162* __restrict__ lo, int mode){
    size_t i = (size_t)blockIdx.x*256 + threadIdx.x;   // one float2 (2 k) per thread
    int r = (int)(i >> 10), cp = (int)(i & 1023);
    float2 v = src[i];
    __nv_bfloat162 h, lw;
    h.x = __float2bfloat16(v.x); h.y = __float2bfloat16(v.y);
    lw.x = __float2bfloat16(v.x - __bfloat162float(h.x));
    lw.y = __float2bfloat16(v.y - __bfloat162float(h.y));
    int p;
    if (mode == 0) p = r;
    else if (mode == 1){ int g = r>>11, j = r&2047; p = (j>>5)*128 + g*32 + (j&31); }
    else             { int g = r>>11, j = r&2047; p = (j>>5)*96  + g*32 + (j&31); }
    hi[(size_t)p*1024 + cp] = h;
    lo[(size_t)p*1024 + cp] = lw;
}

__global__ void setup_kernel(const float* __restrict__ feat){
    int i = blockIdx.x*256 + threadIdx.x;   // 65536 = b*2048 + k
    float v = feat[i];
    d_cf[i] = v; d_hgf[0][i] = v;
    __nv_bfloat16 h = __float2bfloat16(v);
    __nv_bfloat16 l = __float2bfloat16(v - __bfloat162float(h));
    d_hs[0][0][i] = h; d_hs[0][1][i] = l;
    d_hgs[0][0][i] = h; d_hgs[0][1][i] = l;
}

__global__ void xg_kernel(const int* __restrict__ captions, const float* __restrict__ emb,
                          const float* __restrict__ Wih, const float* __restrict__ bih,
                          const float* __restrict__ bhh){
    __shared__ float embS[SE*SB];
    __shared__ float tr[8][32*33];
    int t = blockIdx.x, jc = blockIdx.y, tid = threadIdx.x;
    int lane = tid & 31, wid = tid >> 5;
    for (int i = tid; i < SB*SE; i += 256){
        int b = i / SE, e = i % SE;
        int cap = captions[b*40 + t];
        embS[e*SB + b] = emb[(size_t)cap*SE + e];
    }
    __syncthreads();
    for (int rep = 0; rep < 4; rep++){
        int jbase = jc*1024 + rep*256 + wid*32;
        for (int jj = 0; jj < 32; jj++){
            int j = jbase + jj;
            float acc = bih[j] + bhh[j];
            const float* wr = Wih + (size_t)j*SE;
            #pragma unroll
            for (int e = 0; e < SE; e++) acc = fmaf(wr[e], embS[e*SB + lane], acc);
            tr[wid][jj*33 + lane] = acc;
        }
        __syncwarp();
        int g = jbase >> 11, col0 = jbase & 2047;
        for (int r = 0; r < 32; r++)
            d_Xg[((size_t)(t*4 + g)*SB + r)*SH + col0 + lane] = tr[wid][lane*33 + r];
        __syncwarp();
    }
}

// ---------------- pipelined bf16x3 GEMM core (M=MR, N=32, K=2048) ----------------
template<int MR, int NTHR>
__device__ __forceinline__ void gemm_run(
    const __nv_bfloat16* __restrict__ Ahi, const __nv_bfloat16* __restrict__ Alo,
    const __nv_bfloat16* __restrict__ Bhi, const __nv_bfloat16* __restrict__ Blo,
    int m0, int rowClamp, uint32_t smb, float c[4][4])
{
    const int ASPL = MR*128;
    const int SS = 2*ASPL + 8192;
    int tid = threadIdx.x, l = tid & 31, w = tid >> 5;
    auto load_stage = [&](int s, int ck){
        uint32_t base = smb + s*SS;
        int k0 = ck*64;
        for (int i = tid; i < 2*MR*8; i += NTHR){
            int split = i / (MR*8), idx = i % (MR*8);
            int row = idx >> 3, cc = idx & 7;
            int gr = m0 + row; if (gr > rowClamp) gr = rowClamp;
            const __nv_bfloat16* src = (split ? Alo : Ahi) + (size_t)gr*SH + k0 + cc*8;
            cpa(base + split*ASPL + row*128 + ((cc ^ (row&7))<<4), src);
        }
        for (int i = tid; i < 512; i += NTHR){
            int split = i >> 8, idx = i & 255;
            int n = idx >> 3, cc = idx & 7;
            const __nv_bfloat16* src = (split ? Blo : Bhi) + (size_t)n*SH + k0 + cc*8;
            cpa(base + 2*ASPL + split*4096 + n*128 + ((cc ^ (n&7))<<4), src);
        }
        CP_COMMIT;
    };
    load_stage(0,0); load_stage(1,1);
    int rowA = w*16 + (l & 15);
    int nB0 = (l&7) + ((l&16)>>1);
    int cAdd = l >> 4, cBadd = (l>>3)&1;
    for (int ck = 0; ck < 32; ck++){
        if (ck == 31){ CP_WAIT0; } else { CP_WAIT1; }
        __syncthreads();
        if (ck + 2 < 32) load_stage((ck+2)%3, ck+2);
        uint32_t ab = smb + (ck%3)*SS;
        uint32_t bb = ab + 2*ASPL;
        #pragma unroll
        for (int ks = 0; ks < 4; ks++){
            uint32_t ah[4], al[4];
            int cuA = ks*2 + cAdd;
            uint32_t aaddr = ab + rowA*128 + ((cuA ^ (rowA&7))<<4);
            ldm4(ah, aaddr);
            ldm4(al, aaddr + ASPL);
            #pragma unroll
            for (int g = 0; g < 2; g++){
                uint32_t bh[4], bl[4];
                int n = g*16 + nB0;
                int cuB = ks*2 + cBadd;
                uint32_t baddr = bb + n*128 + ((cuB ^ (n&7))<<4);
                ldm4(bh, baddr);
                ldm4(bl, baddr + 4096);
                hmma(c[2*g],   ah, bh);
                hmma(c[2*g],   ah, bl);
                hmma(c[2*g],   al, bh);
                hmma(c[2*g+1], ah, bh+2);
                hmma(c[2*g+1], ah, bl+2);
                hmma(c[2*g+1], al, bh+2);
            }
        }
        __syncthreads();
    }
}

// ---------------- mmaA: LSTM (64 blocks, fused ew) + GRU-hidden (48 blocks) ----------------
#define SMEM_STEP  ((2*128*128 + 8192)*3)
#define SMEM_STEPB ((2*96*128 + 8192)*3)

__global__ void __launch_bounds__(256) mmaA_kernel(int t){
    extern __shared__ char sm[];
    uint32_t smb = s2u(sm);
    int rp = t & 1, wp = rp ^ 1;
    int tid = threadIdx.x, l = tid & 31, w = tid >> 5;
    float c[4][4];
    #pragma unroll
    for (int i = 0; i < 4; i++){ c[i][0]=0.f; c[i][1]=0.f; c[i][2]=0.f; c[i][3]=0.f; }
    int t4 = l >> 2, cb = (l & 3)*2;
    if (blockIdx.x < 64){
        int vb = blockIdx.x;
        gemm_run<128,256>(g_wLhi, g_wLlo, d_hs[rp][0], d_hs[rp][1], vb*128, 8191, smb, c);
        float* ex = (float*)sm;
        #pragma unroll
        for (int nt = 0; nt < 4; nt++){
            #pragma unroll
            for (int p = 0; p < 2; p++){
                int r = w*16 + t4 + p*8, col = nt*8 + cb;
                ex[r*33 + col]     = c[nt][2*p];
                ex[r*33 + col + 1] = c[nt][2*p+1];
            }
        }
        __syncthreads();
        #pragma unroll
        for (int it = 0; it < 4; it++){
            int id = it*256 + tid;
            int b = id >> 5, jl = id & 31;
            int jg = vb*32 + jl;
            float gi = ex[(     jl)*33 + b] + d_Xg[((size_t)(t*4+0)*SB + b)*SH + jg];
            float gf = ex[(32 + jl)*33 + b] + d_Xg[((size_t)(t*4+1)*SB + b)*SH + jg];
            float gg = ex[(64 + jl)*33 + b] + d_Xg[((size_t)(t*4+2)*SB + b)*SH + jg];
            float go = ex[(96 + jl)*33 + b] + d_Xg[((size_t)(t*4+3)*SB + b)*SH + jg];
            float cold = d_cf[b*SH + jg];
            float cn = sigf(gf)*cold + sigf(gi)*tanhf(gg);
            float hn = sigf(go)*tanhf(cn);
            d_cf[b*SH + jg] = cn;
            __nv_bfloat16 h1 = __float2bfloat16(cn);
            d_cs[0][b*SH + jg] = h1;
            d_cs[1][b*SH + jg] = __float2bfloat16(cn - __bfloat162float(h1));
            __nv_bfloat16 h2 = __float2bfloat16(hn);
            d_hs[wp][0][b*SH + jg] = h2;
            d_hs[wp][1][b*SH + jg] = __float2bfloat16(hn - __bfloat162float(h2));
        }
    } else {
        int m0 = (blockIdx.x - 64)*128;
        gemm_run<128,256>(g_gHhi, g_gHlo, d_hgs[rp][0], d_hgs[rp][1], m0, 6143, smb, c);
        #pragma unroll
        for (int nt = 0; nt < 4; nt++){
            #pragma unroll
            for (int p = 0; p < 2; p++){
                int r = m0 + w*16 + t4 + p*8;
                int g = r >> 11, j = r & 2047;
                int b = nt*8 + cb;
                d_preGH[((size_t)(g*SB + b    ))*SH + j] = c[nt][2*p];
                d_preGH[((size_t)(g*SB + b + 1))*SH + j] = c[nt][2*p+1];
            }
        }
    }
}

// ---------------- mmaB: GRU input-side + fused GRU elementwise (64 blocks, 96 rows) ----------------
__global__ void __launch_bounds__(192) mmaB_kernel(const float* __restrict__ gbih,
                                                   const float* __restrict__ gbhh, int t){
    extern __shared__ char sm[];
    uint32_t smb = s2u(sm);
    int rp = t & 1, wp = rp ^ 1;
    int tid = threadIdx.x, l = tid & 31, w = tid >> 5;
    float c[4][4];
    #pragma unroll
    for (int i = 0; i < 4; i++){ c[i][0]=0.f; c[i][1]=0.f; c[i][2]=0.f; c[i][3]=0.f; }
    int vb = blockIdx.x;
    gemm_run<96,192>(g_gIhi, g_gIlo, d_cs[0], d_cs[1], vb*96, 6143, smb, c);
    float* ex = (float*)sm;
    int t4 = l >> 2, cb = (l & 3)*2;
    #pragma unroll
    for (int nt = 0; nt < 4; nt++){
        #pragma unroll
        for (int p = 0; p < 2; p++){
            int r = w*16 + t4 + p*8, col = nt*8 + cb;
            ex[r*33 + col]     = c[nt][2*p];
            ex[r*33 + col + 1] = c[nt][2*p+1];
        }
    }
    __syncthreads();
    for (int id = tid; id < 1024; id += 192){
        int b = id >> 5, jl = id & 31;
        int jg = vb*32 + jl;
        float gi0 = ex[(     jl)*33 + b] + gbih[jg];
        float gi1 = ex[(32 + jl)*33 + b] + gbih[SH + jg];
        float gi2 = ex[(64 + jl)*33 + b] + gbih[2*SH + jg];
        float gh0 = d_preGH[((size_t)(0*SB + b))*SH + jg] + gbhh[jg];
        float gh1 = d_preGH[((size_t)(1*SB + b))*SH + jg] + gbhh[SH + jg];
        float gh2 = d_preGH[((size_t)(2*SB + b))*SH + jg] + gbhh[2*SH + jg];
        float r_ = sigf(gi0 + gh0);
        float z_ = sigf(gi1 + gh1);
        float n_ = tanhf(gi2 + r_*gh2);
        float hgo = d_hgf[rp][b*SH + jg];
        float hg = (1.0f - z_)*n_ + z_*hgo;
        d_hgf[wp][b*SH + jg] = hg;
        __nv_bfloat16 hh = __float2bfloat16(hg);
        __nv_bfloat16 hl = __float2bfloat16(hg - __bfloat162float(hh));
        d_hgs[wp][0][b*SH + jg] = hh;
        d_hgs[wp][1][b*SH + jg] = hl;
        size_t ai = ((size_t)t*SB + b)*SH + jg;
        d_hgA[0][ai] = hh; d_hgA[1][ai] = hl;
    }
}

// ---------------- final projection: M=128 x N=128 (4 timesteps) ----------------
#define SMEM_FIN (65536*3)

__global__ void __launch_bounds__(256) mmaF_kernel(const float* __restrict__ linb,
                                                   float* __restrict__ out){
    extern __shared__ char sm[];
    uint32_t smb = s2u(sm);
    int tid = threadIdx.x, l = tid & 31, w = tid >> 5;
    int m0 = blockIdx.x*128;
    int tg = blockIdx.y, t0 = tg*4;
    int Nact = (tg == 9) ? 96 : 128;
    const __nv_bfloat16* Bh = d_hgA[0] + (size_t)t0*SB*SH;
    const __nv_bfloat16* Bl = d_hgA[1] + (size_t)t0*SB*SH;
    const int ASPL = 16384, BSPL = 16384, SS = 65536;
    float c[16][4];
    #pragma unroll
    for (int i = 0; i < 16; i++){ c[i][0]=0.f; c[i][1]=0.f; c[i][2]=0.f; c[i][3]=0.f; }
    auto load_stage = [&](int s, int ck){
        uint32_t base = smb + s*SS;
        int k0 = ck*64;
        #pragma unroll
        for (int p = 0; p < 8; p++){
            int i = p*256 + tid;
            int split = i >> 10, idx = i & 1023;
            int row = idx >> 3, cc = idx & 7;
            int gr = m0 + row; if (gr > SV-1) gr = SV-1;
            const __nv_bfloat16* src = (split ? g_lnlo : g_lnhi) + (size_t)gr*SH + k0 + cc*8;
            cpa(base + split*ASPL + row*128 + ((cc ^ (row&7))<<4), src);
        }
        #pragma unroll
        for (int p = 0; p < 8; p++){
            int i = p*256 + tid;
            int split = i >> 10, idx = i & 1023;
            int n = idx >> 3, cc = idx & 7;
            int gn = n; if (gn >= Nact) gn = Nact - 1;
            const __nv_bfloat16* src = (split ? Bl : Bh) + (size_t)gn*SH + k0 + cc*8;
            cpa(base + 2*ASPL + split*BSPL + n*128 + ((cc ^ (n&7))<<4), src);
        }
        CP_COMMIT;
    };
    load_stage(0,0); load_stage(1,1);
    int rowA = w*16 + (l & 15);
    int nB0 = (l&7) + ((l&16)>>1);
    int cAdd = l >> 4, cBadd = (l>>3)&1;
    for (int ck = 0; ck < 32; ck++){
        if (ck == 31){ CP_WAIT0; } else { CP_WAIT1; }
        __syncthreads();
        if (ck + 2 < 32) load_stage((ck+2)%3, ck+2);
        uint32_t ab = smb + (ck%3)*SS;
        uint32_t bb = ab + 2*ASPL;
        #pragma unroll
        for (int ks = 0; ks < 4; ks++){
            uint32_t ah[4], al[4];
            int cuA = ks*2 + cAdd;
            uint32_t aaddr = ab + rowA*128 + ((cuA ^ (rowA&7))<<4);
            ldm4(ah, aaddr);
            ldm4(al, aaddr + ASPL);
            #pragma unroll
            for (int g = 0; g < 8; g++){
                uint32_t bh[4], bl[4];
                int n = g*16 + nB0;
                int cuB = ks*2 + cBadd;
                uint32_t baddr = bb + n*128 + ((cuB ^ (n&7))<<4);
                ldm4(bh, baddr);
                ldm4(bl, baddr + BSPL);
                hmma(c[2*g],   ah, bh);
                hmma(c[2*g],   ah, bl);
                hmma(c[2*g],   al, bh);
                hmma(c[2*g+1], ah, bh+2);
                hmma(c[2*g+1], ah, bl+2);
                hmma(c[2*g+1], al, bh+2);
            }
        }
        __syncthreads();
    }
    int validT = (tg == 9) ? 3 : 4;
    int t4 = l >> 2, cb = (l & 3)*2;
    #pragma unroll
    for (int nt = 0; nt < 16; nt++){
        int col = nt*8 + cb;
        int tl = col >> 5, b = col & 31;
        if (tl >= validT) continue;
        int tt = t0 + tl;
        #pragma unroll
        for (int p = 0; p < 2; p++){
            int v = m0 + w*16 + t4 + p*8;
            if (v < SV){
                float bias = linb[v];
                size_t o = (size_t)b*((size_t)ST*SV) + (size_t)tt*SV + v;
                out[o] = c[nt][2*p] + bias;
                out[o + (size_t)ST*SV] = c[nt][2*p+1] + bias;
            }
        }
    }
}

// ---------------- launch ----------------
extern "C" void kernel_launch(void* const* d_in, const int* in_sizes, int n_in,
                              void* d_out, int out_size){
    const float* features = (const float*)d_in[0];
    const int*   captions = (const int*)  d_in[1];
    const float* emb      = (const float*)d_in[2];
    const float* lWih     = (const float*)d_in[3];
    const float* lbih     = (const float*)d_in[4];
    const float* lWhh     = (const float*)d_in[5];
    const float* lbhh     = (const float*)d_in[6];
    const float* gWih     = (const float*)d_in[7];
    const float* gbih     = (const float*)d_in[8];
    const float* gWhh     = (const float*)d_in[9];
    const float* gbhh     = (const float*)d_in[10];
    const float* linW     = (const float*)d_in[11];
    const float* linb     = (const float*)d_in[12];
    float* out = (float*)d_out;

    cudaFuncSetAttribute(mmaA_kernel, cudaFuncAttributeMaxDynamicSharedMemorySize, SMEM_STEP);
    cudaFuncSetAttribute(mmaB_kernel, cudaFuncAttributeMaxDynamicSharedMemorySize, SMEM_STEPB);
    cudaFuncSetAttribute(mmaF_kernel, cudaFuncAttributeMaxDynamicSharedMemorySize, SMEM_FIN);

    __nv_bfloat162 *pLh, *pLl, *pGHh, *pGHl, *pGIh, *pGIl, *pNh, *pNl;
    cudaGetSymbolAddress((void**)&pLh,  g_wLhi); cudaGetSymbolAddress((void**)&pLl,  g_wLlo);
    cudaGetSymbolAddress((void**)&pGHh, g_gHhi); cudaGetSymbolAddress((void**)&pGHl, g_gHlo);
    cudaGetSymbolAddress((void**)&pGIh, g_gIhi); cudaGetSymbolAddress((void**)&pGIl, g_gIlo);
    cudaGetSymbolAddress((void**)&pNh,  g_lnhi); cudaGetSymbolAddress((void**)&pNl,  g_lnlo);

    setup_kernel<<<256, 256>>>(features);
    splitw_kernel<<<32768, 256>>>((const float2*)lWhh, pLh, pLl, 1);
    splitw_kernel<<<24576, 256>>>((const float2*)gWhh, pGHh, pGHl, 0);
    splitw_kernel<<<24576, 256>>>((const float2*)gWih, pGIh, pGIl, 2);
    splitw_kernel<<<32000, 256>>>((const float2*)linW, pNh, pNl, 0);
    xg_kernel<<<dim3(ST, 8), 256>>>(captions, emb, lWih, lbih, lbhh);

    for (int t = 0; t < ST; t++){
        mmaA_kernel<<<112, 256, SMEM_STEP>>>(t);
        mmaB_kernel<<<64, 192, SMEM_STEPB>>>(gbih, gbhh, t);
    }
    mmaF_kernel<<<dim3(63, 10), 256, SMEM_FIN>>>(linb, out);
}

// round 11
// speedup vs baseline: 3.0683x; 1.3076x over previous
#include <cuda_runtime.h>
#include <cuda_bf16.h>
#include <math.h>
#include <stdint.h>

#define SB 32
#define SH 2048
#define ST 39
#define SV 8000
#define SE 50

__device__ __forceinline__ float sigf(float x){ return 1.0f/(1.0f + expf(-x)); }

__device__ __forceinline__ uint32_t s2u(const void* p){
    uint32_t a; asm("{ .reg .u64 t; cvta.to.shared.u64 t, %1; cvt.u32.u64 %0, t; }" : "=r"(a) : "l"(p)); return a;
}
__device__ __forceinline__ void minit(uint32_t m, uint32_t c){
    asm volatile("mbarrier.init.shared.b64 [%0], %1;" :: "r"(m), "r"(c) : "memory");
}
__device__ __forceinline__ void mexpect(uint32_t m, uint32_t tx){
    asm volatile("mbarrier.arrive.expect_tx.shared.b64 _, [%0], %1;" :: "r"(m), "r"(tx) : "memory");
}
__device__ __forceinline__ void mwait(uint32_t m, uint32_t ph){
    asm volatile("{ .reg .pred P; L%=: mbarrier.try_wait.parity.acquire.cta.shared::cta.b64 P, [%0], %1; @P bra D%=; bra L%=; D%=: }"
                 :: "r"(m), "r"(ph) : "memory");
}
__device__ __forceinline__ void bulkcp(uint32_t dst, const void* src, uint32_t bytes, uint32_t mbar){
    asm volatile("cp.async.bulk.shared::cluster.global.mbarrier::complete_tx::bytes [%0], [%1], %2, [%3];"
                 :: "r"(dst), "l"(src), "r"(bytes), "r"(mbar) : "memory");
}
__device__ __forceinline__ void ldm4(uint32_t* r, uint32_t a){
    asm volatile("ldmatrix.sync.aligned.m8n8.x4.shared.b16 {%0,%1,%2,%3}, [%4];"
        : "=r"(r[0]),"=r"(r[1]),"=r"(r[2]),"=r"(r[3]) : "r"(a));
}
__device__ __forceinline__ void hmma(float* c, const uint32_t* a, const uint32_t* b){
    asm volatile("mma.sync.aligned.m16n8k16.row.col.f32.bf16.bf16.f32 "
        "{%0,%1,%2,%3}, {%4,%5,%6,%7}, {%8,%9}, {%0,%1,%2,%3};"
        : "+f"(c[0]),"+f"(c[1]),"+f"(c[2]),"+f"(c[3])
        : "r"(a[0]),"r"(a[1]),"r"(a[2]),"r"(a[3]), "r"(b[0]),"r"(b[1]));
}

// ---------------- packed weights: [mblk][ck(32)][split(2)][row(MR)][64k swizzled 128B] ----------------
__device__ __align__(128) __nv_bfloat16 g_LP[(size_t)64*32*2*128*64];   // LSTM Whh, gate-permuted
__device__ __align__(128) __nv_bfloat16 g_HP[(size_t)48*32*2*128*64];   // GRU Whh
__device__ __align__(128) __nv_bfloat16 g_IP[(size_t)64*32*2*96*64];    // GRU Wih, gate-permuted, MR=96
__device__ __align__(128) __nv_bfloat16 g_FP[(size_t)63*32*2*128*64];   // linW (rows >=8000 zero)
// packed states: [ck(32)][split(2)][n][64k swizzled]
__device__ __align__(128) __nv_bfloat16 d_hsP [2][32*2*32*64];
__device__ __align__(128) __nv_bfloat16 d_hgsP[2][32*2*32*64];
__device__ __align__(128) __nv_bfloat16 d_csP [32*2*32*64];
__device__ __align__(128) __nv_bfloat16 d_FBP[(size_t)10*32*2*128*64];  // final B, tg of 4 timesteps
__device__ __align__(16) float d_Xg[(size_t)ST*4*SB*SH];     // [t][gate][b][k]
__device__ __align__(16) float d_cf[SB*SH];                  // [b][k]
__device__ __align__(16) float d_hgf[2][SB*SH];              // [b][k]
__device__ __align__(16) float d_preGH[3*SB*SH];             // [gate][b][k]

// ---------------- prep ----------------
// pack fp32 weight [Rtot][2048] -> hi/lo packed tiles. mode:0 ident,1 LSTM,2 GRU
__global__ void packw_kernel(const float* __restrict__ src, __nv_bfloat16* __restrict__ dst,
                             int mode, int MR){
    int i = blockIdx.x*256 + threadIdx.x;
    int r = i >> 8, u = i & 255;
    int k = u*8, ck = k >> 6, cc = (k >> 3) & 7;
    int p;
    if (mode == 0) p = r;
    else if (mode == 1){ int g = r>>11, j = r&2047; p = (j>>5)*128 + g*32 + (j&31); }
    else             { int g = r>>11, j = r&2047; p = (j>>5)*96  + g*32 + (j&31); }
    int mblk = p / MR, row = p % MR;
    size_t base = ((size_t)mblk*32 + ck)*(2*(size_t)MR*64) + (size_t)row*64 + ((cc^(row&7))*8);
    const float4* s4 = (const float4*)(src + (size_t)r*SH + k);
    float4 v0 = s4[0], v1 = s4[1];
    float f[8] = {v0.x,v0.y,v0.z,v0.w,v1.x,v1.y,v1.z,v1.w};
    __nv_bfloat16 hi[8], lo[8];
    #pragma unroll
    for (int q = 0; q < 8; q++){
        hi[q] = __float2bfloat16(f[q]);
        lo[q] = __float2bfloat16(f[q] - __bfloat162float(hi[q]));
    }
    *(uint4*)(dst + base) = *(uint4*)hi;
    *(uint4*)(dst + base + (size_t)MR*64) = *(uint4*)lo;
}

__device__ __forceinline__ size_t pkidx32(int b, int jg, int split){
    int ck = jg >> 6, kk = jg & 63, cc = kk >> 3;
    return (size_t)(ck*2 + split)*2048 + b*64 + ((cc^(b&7))*8) + (kk&7);
}

__global__ void setup_kernel(const float* __restrict__ feat){
    int i = blockIdx.x*256 + threadIdx.x;   // 65536 = b*2048 + k
    int b = i >> 11, k = i & 2047;
    float v = feat[i];
    d_cf[i] = v; d_hgf[0][i] = v;
    __nv_bfloat16 h = __float2bfloat16(v);
    __nv_bfloat16 l = __float2bfloat16(v - __bfloat162float(h));
    d_hsP[0][pkidx32(b,k,0)] = h; d_hsP[0][pkidx32(b,k,1)] = l;
    d_hgsP[0][pkidx32(b,k,0)] = h; d_hgsP[0][pkidx32(b,k,1)] = l;
}

__global__ void xg_kernel(const int* __restrict__ captions, const float* __restrict__ emb,
                          const float* __restrict__ Wih, const float* __restrict__ bih,
                          const float* __restrict__ bhh){
    __shared__ float embS[SE*SB];
    __shared__ float tr[8][32*33];
    int t = blockIdx.x, jc = blockIdx.y, tid = threadIdx.x;
    int lane = tid & 31, wid = tid >> 5;
    for (int i = tid; i < SB*SE; i += 256){
        int b = i / SE, e = i % SE;
        int cap = captions[b*40 + t];
        embS[e*SB + b] = emb[(size_t)cap*SE + e];
    }
    __syncthreads();
    for (int rep = 0; rep < 4; rep++){
        int jbase = jc*1024 + rep*256 + wid*32;
        for (int jj = 0; jj < 32; jj++){
            int j = jbase + jj;
            float acc = bih[j] + bhh[j];
            const float* wr = Wih + (size_t)j*SE;
            #pragma unroll
            for (int e = 0; e < SE; e++) acc = fmaf(wr[e], embS[e*SB + lane], acc);
            tr[wid][jj*33 + lane] = acc;
        }
        __syncwarp();
        int g = jbase >> 11, col0 = jbase & 2047;
        for (int r = 0; r < 32; r++)
            d_Xg[((size_t)(t*4 + g)*SB + r)*SH + col0 + lane] = tr[wid][lane*33 + r];
        __syncwarp();
    }
}

// ---------------- bulk-pipelined bf16x3 GEMM core ----------------
// Apk: packed [ck][split][MR][64swz]; Bpk: packed [ck][split][NB][64swz]
template<int MR, int NB, int NTHR>
__device__ __forceinline__ void gemm_bulk(const __nv_bfloat16* __restrict__ Apk,
                                          const __nv_bfloat16* __restrict__ Bpk,
                                          char* sm, float (*c)[4]){
    const int ASZ = 2*MR*128, BSZ = 2*NB*128, SS = ASZ + BSZ;
    const int NST = 3;
    uint32_t smb = s2u(sm);
    uint32_t mb = smb + NST*SS;
    int tid = threadIdx.x, l = tid & 31, w = tid >> 5;
    if (tid == 0){
        #pragma unroll
        for (int s = 0; s < NST; s++) minit(mb + 8*s, 1);
    }
    __syncthreads();
    auto issue = [&](int s, int ck){
        if (tid == 0){
            mexpect(mb + 8*s, (uint32_t)(ASZ + BSZ));
            bulkcp(smb + s*SS,       Apk + (size_t)ck*(2*MR*64), ASZ, mb + 8*s);
            bulkcp(smb + s*SS + ASZ, Bpk + (size_t)ck*(2*NB*64), BSZ, mb + 8*s);
        }
    };
    issue(0,0); issue(1,1); issue(2,2);
    int rowA = w*16 + (l & 15);
    int nB0 = (l&7) + ((l&16)>>1);
    int cAdd = l >> 4, cBadd = (l>>3)&1;
    for (int ck = 0; ck < 32; ck++){
        int s = ck % NST;
        mwait(mb + 8*s, (ck/NST)&1);
        uint32_t ab = smb + s*SS, bb = ab + ASZ;
        #pragma unroll
        for (int ks = 0; ks < 4; ks++){
            uint32_t ah[4], al[4];
            int cuA = ks*2 + cAdd;
            uint32_t aaddr = ab + rowA*128 + ((cuA ^ (rowA&7))<<4);
            ldm4(ah, aaddr);
            ldm4(al, aaddr + MR*128);
            #pragma unroll
            for (int g = 0; g < NB/16; g++){
                uint32_t bh[4], bl[4];
                int n = g*16 + nB0;
                int cuB = ks*2 + cBadd;
                uint32_t baddr = bb + n*128 + ((cuB ^ (n&7))<<4);
                ldm4(bh, baddr);
                ldm4(bl, baddr + NB*128);
                hmma(c[2*g],   ah, bh);
                hmma(c[2*g],   ah, bl);
                hmma(c[2*g],   al, bh);
                hmma(c[2*g+1], ah, bh+2);
                hmma(c[2*g+1], ah, bl+2);
                hmma(c[2*g+1], al, bh+2);
            }
        }
        __syncthreads();
        if (ck + NST < 32) issue(s, ck + NST);
    }
}

// ---------------- mmaA: LSTM (64 blocks, fused ew) + GRU-hidden (48 blocks) ----------------
#define SMEM_STEP  ((2*128*128 + 2*32*128)*3 + 64)
#define SMEM_STEPB ((2*96*128 + 2*32*128)*3 + 64)
#define SMEM_FIN   ((2*128*128 + 2*128*128)*3 + 64)

__global__ void __launch_bounds__(256) mmaA_kernel(int t){
    extern __shared__ char sm[];
    int rp = t & 1, wp = rp ^ 1;
    int tid = threadIdx.x, l = tid & 31, w = tid >> 5;
    float c[4][4];
    #pragma unroll
    for (int i = 0; i < 4; i++){ c[i][0]=0.f; c[i][1]=0.f; c[i][2]=0.f; c[i][3]=0.f; }
    int t4 = l >> 2, cb = (l & 3)*2;
    if (blockIdx.x < 64){
        int vb = blockIdx.x;
        gemm_bulk<128,32,256>(g_LP + (size_t)vb*(32*2*128*64), d_hsP[rp], sm, c);
        __syncthreads();
        float* ex = (float*)sm;
        #pragma unroll
        for (int nt = 0; nt < 4; nt++){
            #pragma unroll
            for (int p = 0; p < 2; p++){
                int r = w*16 + t4 + p*8, col = nt*8 + cb;
                ex[r*33 + col]     = c[nt][2*p];
                ex[r*33 + col + 1] = c[nt][2*p+1];
            }
        }
        __syncthreads();
        #pragma unroll
        for (int it = 0; it < 4; it++){
            int id = it*256 + tid;
            int b = id >> 5, jl = id & 31;
            int jg = vb*32 + jl;
            float gi = ex[(     jl)*33 + b] + d_Xg[((size_t)(t*4+0)*SB + b)*SH + jg];
            float gf = ex[(32 + jl)*33 + b] + d_Xg[((size_t)(t*4+1)*SB + b)*SH + jg];
            float gg = ex[(64 + jl)*33 + b] + d_Xg[((size_t)(t*4+2)*SB + b)*SH + jg];
            float go = ex[(96 + jl)*33 + b] + d_Xg[((size_t)(t*4+3)*SB + b)*SH + jg];
            float cold = d_cf[b*SH + jg];
            float cn = sigf(gf)*cold + sigf(gi)*tanhf(gg);
            float hn = sigf(go)*tanhf(cn);
            d_cf[b*SH + jg] = cn;
            __nv_bfloat16 h1 = __float2bfloat16(cn);
            d_csP[pkidx32(b,jg,0)] = h1;
            d_csP[pkidx32(b,jg,1)] = __float2bfloat16(cn - __bfloat162float(h1));
            __nv_bfloat16 h2 = __float2bfloat16(hn);
            d_hsP[wp][pkidx32(b,jg,0)] = h2;
            d_hsP[wp][pkidx32(b,jg,1)] = __float2bfloat16(hn - __bfloat162float(h2));
        }
    } else {
        int m0 = (blockIdx.x - 64)*128;
        gemm_bulk<128,32,256>(g_HP + (size_t)(blockIdx.x-64)*(32*2*128*64), d_hgsP[rp], sm, c);
        #pragma unroll
        for (int nt = 0; nt < 4; nt++){
            #pragma unroll
            for (int p = 0; p < 2; p++){
                int r = m0 + w*16 + t4 + p*8;
                int g = r >> 11, j = r & 2047;
                int b = nt*8 + cb;
                d_preGH[((size_t)(g*SB + b    ))*SH + j] = c[nt][2*p];
                d_preGH[((size_t)(g*SB + b + 1))*SH + j] = c[nt][2*p+1];
            }
        }
    }
}

// ---------------- mmaB: GRU input-side + fused GRU elementwise ----------------
__global__ void __launch_bounds__(192) mmaB_kernel(const float* __restrict__ gbih,
                                                   const float* __restrict__ gbhh, int t){
    extern __shared__ char sm[];
    int rp = t & 1, wp = rp ^ 1;
    int tid = threadIdx.x, l = tid & 31, w = tid >> 5;
    float c[4][4];
    #pragma unroll
    for (int i = 0; i < 4; i++){ c[i][0]=0.f; c[i][1]=0.f; c[i][2]=0.f; c[i][3]=0.f; }
    int vb = blockIdx.x;
    gemm_bulk<96,32,192>(g_IP + (size_t)vb*(32*2*96*64), d_csP, sm, c);
    __syncthreads();
    float* ex = (float*)sm;
    int t4 = l >> 2, cb = (l & 3)*2;
    #pragma unroll
    for (int nt = 0; nt < 4; nt++){
        #pragma unroll
        for (int p = 0; p < 2; p++){
            int r = w*16 + t4 + p*8, col = nt*8 + cb;
            ex[r*33 + col]     = c[nt][2*p];
            ex[r*33 + col + 1] = c[nt][2*p+1];
        }
    }
    __syncthreads();
    int tg = t >> 2, tl = t & 3;
    for (int id = tid; id < 1024; id += 192){
        int b = id >> 5, jl = id & 31;
        int jg = vb*32 + jl;
        float gi0 = ex[(     jl)*33 + b] + gbih[jg];
        float gi1 = ex[(32 + jl)*33 + b] + gbih[SH + jg];
        float gi2 = ex[(64 + jl)*33 + b] + gbih[2*SH + jg];
        float gh0 = d_preGH[((size_t)(0*SB + b))*SH + jg] + gbhh[jg];
        float gh1 = d_preGH[((size_t)(1*SB + b))*SH + jg] + gbhh[SH + jg];
        float gh2 = d_preGH[((size_t)(2*SB + b))*SH + jg] + gbhh[2*SH + jg];
        float r_ = sigf(gi0 + gh0);
        float z_ = sigf(gi1 + gh1);
        float n_ = tanhf(gi2 + r_*gh2);
        float hgo = d_hgf[rp][b*SH + jg];
        float hg = (1.0f - z_)*n_ + z_*hgo;
        d_hgf[wp][b*SH + jg] = hg;
        __nv_bfloat16 hh = __float2bfloat16(hg);
        __nv_bfloat16 hl = __float2bfloat16(hg - __bfloat162float(hh));
        d_hgsP[wp][pkidx32(b,jg,0)] = hh;
        d_hgsP[wp][pkidx32(b,jg,1)] = hl;
        // final-B packed: n = tl*32 + b, NB=128
        int n = tl*32 + b;
        int ck = jg >> 6, kk = jg & 63, cc = kk >> 3;
        size_t fb = (size_t)tg*(32*2*128*64) + (size_t)(ck*2)*8192 + n*64 + ((cc^(n&7))*8) + (kk&7);
        d_FBP[fb] = hh;
        d_FBP[fb + 8192] = hl;
    }
}

// ---------------- final projection: M=128, N=128 (4 timesteps), 63x10 ----------------
__global__ void __launch_bounds__(256) mmaF_kernel(const float* __restrict__ linb,
                                                   float* __restrict__ out){
    extern __shared__ char sm[];
    int tid = threadIdx.x, l = tid & 31, w = tid >> 5;
    int m0 = blockIdx.x*128;
    int tg = blockIdx.y, t0 = tg*4;
    float c[16][4];
    #pragma unroll
    for (int i = 0; i < 16; i++){ c[i][0]=0.f; c[i][1]=0.f; c[i][2]=0.f; c[i][3]=0.f; }
    gemm_bulk<128,128,256>(g_FP + (size_t)blockIdx.x*(32*2*128*64),
                           d_FBP + (size_t)tg*(32*2*128*64), sm, c);
    int validT = (tg == 9) ? 3 : 4;
    int t4 = l >> 2, cb = (l & 3)*2;
    #pragma unroll
    for (int nt = 0; nt < 16; nt++){
        int col = nt*8 + cb;
        int tl = col >> 5, b = col & 31;
        if (tl >= validT) continue;
        int tt = t0 + tl;
        #pragma unroll
        for (int p = 0; p < 2; p++){
            int v = m0 + w*16 + t4 + p*8;
            if (v < SV){
                float bias = linb[v];
                size_t o = (size_t)b*((size_t)ST*SV) + (size_t)tt*SV + v;
                out[o] = c[nt][2*p] + bias;
                out[o + (size_t)ST*SV] = c[nt][2*p+1] + bias;
            }
        }
    }
}

// ---------------- launch ----------------
extern "C" void kernel_launch(void* const* d_in, const int* in_sizes, int n_in,
                              void* d_out, int out_size){
    const float* features = (const float*)d_in[0];
    const int*   captions = (const int*)  d_in[1];
    const float* emb      = (const float*)d_in[2];
    const float* lWih     = (const float*)d_in[3];
    const float* lbih     = (const float*)d_in[4];
    const float* lWhh     = (const float*)d_in[5];
    const float* lbhh     = (const float*)d_in[6];
    const float* gWih     = (const float*)d_in[7];
    const float* gbih     = (const float*)d_in[8];
    const float* gWhh     = (const float*)d_in[9];
    const float* gbhh     = (const float*)d_in[10];
    const float* linW     = (const float*)d_in[11];
    const float* linb     = (const float*)d_in[12];
    float* out = (float*)d_out;

    cudaFuncSetAttribute(mmaA_kernel, cudaFuncAttributeMaxDynamicSharedMemorySize, SMEM_STEP);
    cudaFuncSetAttribute(mmaB_kernel, cudaFuncAttributeMaxDynamicSharedMemorySize, SMEM_STEPB);
    cudaFuncSetAttribute(mmaF_kernel, cudaFuncAttributeMaxDynamicSharedMemorySize, SMEM_FIN);

    __nv_bfloat16 *pL, *pH, *pI, *pF;
    cudaGetSymbolAddress((void**)&pL, g_LP);
    cudaGetSymbolAddress((void**)&pH, g_HP);
    cudaGetSymbolAddress((void**)&pI, g_IP);
    cudaGetSymbolAddress((void**)&pF, g_FP);

    setup_kernel<<<256, 256>>>(features);
    packw_kernel<<<8192, 256>>>(lWhh, pL, 1, 128);
    packw_kernel<<<6144, 256>>>(gWhh, pH, 0, 128);
    packw_kernel<<<6144, 256>>>(gWih, pI, 2, 96);
    packw_kernel<<<8000, 256>>>(linW, pF, 0, 128);
    xg_kernel<<<dim3(ST, 8), 256>>>(captions, emb, lWih, lbih, lbhh);

    for (int t = 0; t < ST; t++){
        mmaA_kernel<<<112, 256, SMEM_STEP>>>(t);
        mmaB_kernel<<<64, 192, SMEM_STEPB>>>(gbih, gbhh, t);
    }
    mmaF_kernel<<<dim3(63, 10), 256, SMEM_FIN>>>(linb, out);
}

// round 12
// speedup vs baseline: 5.3605x; 1.7471x over previous
#include <cuda_runtime.h>
#include <cuda_fp16.h>
#include <math.h>
#include <stdint.h>

#define SB 32
#define SH 2048
#define ST 39
#define SV 8000
#define SE 50

__device__ __forceinline__ float sigf(float x){ return 1.0f/(1.0f + expf(-x)); }

__device__ __forceinline__ uint32_t s2u(const void* p){
    uint32_t a; asm("{ .reg .u64 t; cvta.to.shared.u64 t, %1; cvt.u32.u64 %0, t; }" : "=r"(a) : "l"(p)); return a;
}
__device__ __forceinline__ void minit(uint32_t m, uint32_t c){
    asm volatile("mbarrier.init.shared.b64 [%0], %1;" :: "r"(m), "r"(c) : "memory");
}
__device__ __forceinline__ void mexpect(uint32_t m, uint32_t tx){
    asm volatile("mbarrier.arrive.expect_tx.shared.b64 _, [%0], %1;" :: "r"(m), "r"(tx) : "memory");
}
__device__ __forceinline__ void mwait(uint32_t m, uint32_t ph){
    asm volatile("{ .reg .pred P; L%=: mbarrier.try_wait.parity.acquire.cta.shared::cta.b64 P, [%0], %1; @P bra D%=; bra L%=; D%=: }"
                 :: "r"(m), "r"(ph) : "memory");
}
__device__ __forceinline__ void bulkcp(uint32_t dst, const void* src, uint32_t bytes, uint32_t mbar){
    asm volatile("cp.async.bulk.shared::cluster.global.mbarrier::complete_tx::bytes [%0], [%1], %2, [%3];"
                 :: "r"(dst), "l"(src), "r"(bytes), "r"(mbar) : "memory");
}
__device__ __forceinline__ void ldm4(uint32_t* r, uint32_t a){
    asm volatile("ldmatrix.sync.aligned.m8n8.x4.shared.b16 {%0,%1,%2,%3}, [%4];"
        : "=r"(r[0]),"=r"(r[1]),"=r"(r[2]),"=r"(r[3]) : "r"(a));
}
__device__ __forceinline__ void hmma(float* c, const uint32_t* a, const uint32_t* b){
    asm volatile("mma.sync.aligned.m16n8k16.row.col.f32.f16.f16.f32 "
        "{%0,%1,%2,%3}, {%4,%5,%6,%7}, {%8,%9}, {%0,%1,%2,%3};"
        : "+f"(c[0]),"+f"(c[1]),"+f"(c[2]),"+f"(c[3])
        : "r"(a[0]),"r"(a[1]),"r"(a[2]),"r"(a[3]), "r"(b[0]),"r"(b[1]));
}

// ---------------- packed fp16 weights: [mblk][ck64(32)][row(MR)][64k swizzled 128B] ----------------
__device__ __align__(128) __half g_LP[(size_t)64*32*128*64];   // LSTM Whh, gate-permuted
__device__ __align__(128) __half g_HP[(size_t)48*32*128*64];   // GRU Whh
__device__ __align__(128) __half g_IP[(size_t)64*32*96*64];    // GRU Wih, gate-permuted, MR=96
__device__ __align__(128) __half g_FP[(size_t)63*32*128*64];   // linW (rows >=8000 zero-clamped)
// packed fp16 states: [ck64(32)][n][64k swizzled]
__device__ __align__(128) __half d_hsP [2][32*32*64];
__device__ __align__(128) __half d_hgsP[2][32*32*64];
__device__ __align__(128) __half d_csP [32*32*64];
__device__ __align__(128) __half d_FBP[(size_t)10*32*128*64];  // final B, tg of 4 timesteps
__device__ __align__(16) float d_Xg[(size_t)ST*4*SB*SH];     // [t][gate][b][k]
__device__ __align__(16) float d_cf[SB*SH];                  // [b][k]
__device__ __align__(16) float d_hgf[2][SB*SH];              // [b][k]
__device__ __align__(16) float d_preGH[3*SB*SH];             // [gate][b][k]

// ---------------- prep ----------------
__global__ void packw_kernel(const float* __restrict__ src, __half* __restrict__ dst,
                             int mode, int MR){
    int i = blockIdx.x*256 + threadIdx.x;
    int r = i >> 8, u = i & 255;
    int k = u*8, ck = k >> 6, cc = (k >> 3) & 7;
    int p;
    if (mode == 0) p = r;
    else if (mode == 1){ int g = r>>11, j = r&2047; p = (j>>5)*128 + g*32 + (j&31); }
    else             { int g = r>>11, j = r&2047; p = (j>>5)*96  + g*32 + (j&31); }
    int mblk = p / MR, row = p % MR;
    size_t base = ((size_t)mblk*32 + ck)*((size_t)MR*64) + (size_t)row*64 + ((cc^(row&7))*8);
    const float4* s4 = (const float4*)(src + (size_t)r*SH + k);
    float4 v0 = s4[0], v1 = s4[1];
    float f[8] = {v0.x,v0.y,v0.z,v0.w,v1.x,v1.y,v1.z,v1.w};
    __half h[8];
    #pragma unroll
    for (int q = 0; q < 8; q++) h[q] = __float2half(f[q]);
    *(uint4*)(dst + base) = *(uint4*)h;
}

__device__ __forceinline__ int pkidx32(int b, int jg){
    int ck = jg >> 6, kk = jg & 63, cc = kk >> 3;
    return ck*2048 + b*64 + ((cc^(b&7))*8) + (kk&7);
}

__global__ void setup_kernel(const float* __restrict__ feat){
    int i = blockIdx.x*256 + threadIdx.x;   // 65536 = b*2048 + k
    int b = i >> 11, k = i & 2047;
    float v = feat[i];
    d_cf[i] = v; d_hgf[0][i] = v;
    __half h = __float2half(v);
    d_hsP[0][pkidx32(b,k)] = h;
    d_hgsP[0][pkidx32(b,k)] = h;
}

__global__ void xg_kernel(const int* __restrict__ captions, const float* __restrict__ emb,
                          const float* __restrict__ Wih, const float* __restrict__ bih,
                          const float* __restrict__ bhh){
    __shared__ float embS[SE*SB];
    __shared__ float tr[8][32*33];
    int t = blockIdx.x, jc = blockIdx.y, tid = threadIdx.x;
    int lane = tid & 31, wid = tid >> 5;
    for (int i = tid; i < SB*SE; i += 256){
        int b = i / SE, e = i % SE;
        int cap = captions[b*40 + t];
        embS[e*SB + b] = emb[(size_t)cap*SE + e];
    }
    __syncthreads();
    for (int rep = 0; rep < 4; rep++){
        int jbase = jc*1024 + rep*256 + wid*32;
        for (int jj = 0; jj < 32; jj++){
            int j = jbase + jj;
            float acc = bih[j] + bhh[j];
            const float* wr = Wih + (size_t)j*SE;
            #pragma unroll
            for (int e = 0; e < SE; e++) acc = fmaf(wr[e], embS[e*SB + lane], acc);
            tr[wid][jj*33 + lane] = acc;
        }
        __syncwarp();
        int g = jbase >> 11, col0 = jbase & 2047;
        for (int r = 0; r < 32; r++)
            d_Xg[((size_t)(t*4 + g)*SB + r)*SH + col0 + lane] = tr[wid][lane*33 + r];
        __syncwarp();
    }
}

// ---------------- bulk-pipelined fp16 GEMM core ----------------
// Apk: [ck64][MR][64swz] halfs; Bpk: [ck64][NB][64swz] halfs.
// KC = k per pipeline chunk (64 or 128). G = KC/64 granules per chunk.
template<int MR, int NB, int KC, int NST>
__device__ __forceinline__ void gemm_bulk(const __half* __restrict__ Apk,
                                          const __half* __restrict__ Bpk,
                                          char* sm, float (*c)[4]){
    const int G = KC/64;
    const int ASZ = G*MR*128, BSZ = G*NB*128, SS = ASZ + BSZ;
    const int NCH = 2048/KC;
    uint32_t smb = s2u(sm);
    uint32_t mb = smb + NST*SS;
    int tid = threadIdx.x, l = tid & 31, w = tid >> 5;
    if (tid == 0){
        #pragma unroll
        for (int s = 0; s < NST; s++) minit(mb + 8*s, 1);
    }
    __syncthreads();
    auto issue = [&](int s, int ck){
        if (tid == 0){
            mexpect(mb + 8*s, (uint32_t)(ASZ + BSZ));
            bulkcp(smb + s*SS,       Apk + (size_t)ck*(G*MR*64), ASZ, mb + 8*s);
            bulkcp(smb + s*SS + ASZ, Bpk + (size_t)ck*(G*NB*64), BSZ, mb + 8*s);
        }
    };
    #pragma unroll
    for (int s = 0; s < NST; s++) issue(s, s);
    int rowA = w*16 + (l & 15);
    int nB0 = (l&7) + ((l&16)>>1);
    int cAdd = l >> 4, cBadd = (l>>3)&1;
    for (int ck = 0; ck < NCH; ck++){
        int s = ck % NST;
        mwait(mb + 8*s, (ck/NST)&1);
        uint32_t ab = smb + s*SS, bb = ab + ASZ;
        #pragma unroll
        for (int ks = 0; ks < KC/16; ks++){
            int gA = ks >> 2, cu = (ks & 3)*2;
            uint32_t a4[4];
            uint32_t aaddr = ab + gA*MR*128 + rowA*128 + (((cu + cAdd) ^ (rowA&7))<<4);
            ldm4(a4, aaddr);
            #pragma unroll
            for (int g = 0; g < NB/16; g++){
                uint32_t b4[4];
                int n = g*16 + nB0;
                uint32_t baddr = bb + gA*NB*128 + n*128 + (((cu + cBadd) ^ (n&7))<<4);
                ldm4(b4, baddr);
                hmma(c[2*g],   a4, b4);
                hmma(c[2*g+1], a4, b4+2);
            }
        }
        __syncthreads();
        if (ck + NST < NCH) issue(s, ck + NST);
    }
}

// ---------------- smem sizes ----------------
#define SMEM_STEP  ((2*128*128 + 2*32*128)*3 + 64)    // KC=128: A 32K + B 8K, x3
#define SMEM_STEPB ((2*96*128 + 2*32*128)*3 + 64)     // KC=128: A 24K + B 8K, x3
#define SMEM_FIN   ((2*128*128 + 2*128*128)*3 + 64)   // KC=128: A 32K + B 32K, x3

// ---------------- mmaA: LSTM (64 blocks, fused ew) + GRU-hidden (48 blocks) ----------------
__global__ void __launch_bounds__(256) mmaA_kernel(int t){
    extern __shared__ char sm[];
    int rp = t & 1, wp = rp ^ 1;
    int tid = threadIdx.x, l = tid & 31, w = tid >> 5;
    float c[4][4];
    #pragma unroll
    for (int i = 0; i < 4; i++){ c[i][0]=0.f; c[i][1]=0.f; c[i][2]=0.f; c[i][3]=0.f; }
    int t4 = l >> 2, cb = (l & 3)*2;
    if (blockIdx.x < 64){
        int vb = blockIdx.x;
        gemm_bulk<128,32,128,3>(g_LP + (size_t)vb*(32*128*64), d_hsP[rp], sm, c);
        __syncthreads();
        float* ex = (float*)sm;
        #pragma unroll
        for (int nt = 0; nt < 4; nt++){
            #pragma unroll
            for (int p = 0; p < 2; p++){
                int r = w*16 + t4 + p*8, col = nt*8 + cb;
                ex[r*33 + col]     = c[nt][2*p];
                ex[r*33 + col + 1] = c[nt][2*p+1];
            }
        }
        __syncthreads();
        #pragma unroll
        for (int it = 0; it < 4; it++){
            int id = it*256 + tid;
            int b = id >> 5, jl = id & 31;
            int jg = vb*32 + jl;
            float gi = ex[(     jl)*33 + b] + d_Xg[((size_t)(t*4+0)*SB + b)*SH + jg];
            float gf = ex[(32 + jl)*33 + b] + d_Xg[((size_t)(t*4+1)*SB + b)*SH + jg];
            float gg = ex[(64 + jl)*33 + b] + d_Xg[((size_t)(t*4+2)*SB + b)*SH + jg];
            float go = ex[(96 + jl)*33 + b] + d_Xg[((size_t)(t*4+3)*SB + b)*SH + jg];
            float cold = d_cf[b*SH + jg];
            float cn = sigf(gf)*cold + sigf(gi)*tanhf(gg);
            float hn = sigf(go)*tanhf(cn);
            d_cf[b*SH + jg] = cn;
            d_csP[pkidx32(b,jg)] = __float2half(cn);
            d_hsP[wp][pkidx32(b,jg)] = __float2half(hn);
        }
    } else {
        int m0 = (blockIdx.x - 64)*128;
        gemm_bulk<128,32,128,3>(g_HP + (size_t)(blockIdx.x-64)*(32*128*64), d_hgsP[rp], sm, c);
        #pragma unroll
        for (int nt = 0; nt < 4; nt++){
            #pragma unroll
            for (int p = 0; p < 2; p++){
                int r = m0 + w*16 + t4 + p*8;
                int g = r >> 11, j = r & 2047;
                int b = nt*8 + cb;
                d_preGH[((size_t)(g*SB + b    ))*SH + j] = c[nt][2*p];
                d_preGH[((size_t)(g*SB + b + 1))*SH + j] = c[nt][2*p+1];
            }
        }
    }
}

// ---------------- mmaB: GRU input-side + fused GRU elementwise ----------------
__global__ void __launch_bounds__(192) mmaB_kernel(const float* __restrict__ gbih,
                                                   const float* __restrict__ gbhh, int t){
    extern __shared__ char sm[];
    int rp = t & 1, wp = rp ^ 1;
    int tid = threadIdx.x, l = tid & 31, w = tid >> 5;
    float c[4][4];
    #pragma unroll
    for (int i = 0; i < 4; i++){ c[i][0]=0.f; c[i][1]=0.f; c[i][2]=0.f; c[i][3]=0.f; }
    int vb = blockIdx.x;
    gemm_bulk<96,32,128,3>(g_IP + (size_t)vb*(32*96*64), d_csP, sm, c);
    __syncthreads();
    float* ex = (float*)sm;
    int t4 = l >> 2, cb = (l & 3)*2;
    #pragma unroll
    for (int nt = 0; nt < 4; nt++){
        #pragma unroll
        for (int p = 0; p < 2; p++){
            int r = w*16 + t4 + p*8, col = nt*8 + cb;
            ex[r*33 + col]     = c[nt][2*p];
            ex[r*33 + col + 1] = c[nt][2*p+1];
        }
    }
    __syncthreads();
    int tg = t >> 2, tl = t & 3;
    for (int id = tid; id < 1024; id += 192){
        int b = id >> 5, jl = id & 31;
        int jg = vb*32 + jl;
        float gi0 = ex[(     jl)*33 + b] + gbih[jg];
        float gi1 = ex[(32 + jl)*33 + b] + gbih[SH + jg];
        float gi2 = ex[(64 + jl)*33 + b] + gbih[2*SH + jg];
        float gh0 = d_preGH[((size_t)(0*SB + b))*SH + jg] + gbhh[jg];
        float gh1 = d_preGH[((size_t)(1*SB + b))*SH + jg] + gbhh[SH + jg];
        float gh2 = d_preGH[((size_t)(2*SB + b))*SH + jg] + gbhh[2*SH + jg];
        float r_ = sigf(gi0 + gh0);
        float z_ = sigf(gi1 + gh1);
        float n_ = tanhf(gi2 + r_*gh2);
        float hgo = d_hgf[rp][b*SH + jg];
        float hg = (1.0f - z_)*n_ + z_*hgo;
        d_hgf[wp][b*SH + jg] = hg;
        __half hh = __float2half(hg);
        d_hgsP[wp][pkidx32(b,jg)] = hh;
        // final-B packed: n = tl*32 + b, NB=128
        int n = tl*32 + b;
        int ck = jg >> 6, kk = jg & 63, cc = kk >> 3;
        size_t fb = (size_t)tg*(32*128*64) + (size_t)ck*(128*64) + n*64 + ((cc^(n&7))*8) + (kk&7);
        d_FBP[fb] = hh;
    }
}

// ---------------- final projection: M=128, N=128 (4 timesteps), 63x10 ----------------
__global__ void __launch_bounds__(256) mmaF_kernel(const float* __restrict__ linb,
                                                   float* __restrict__ out){
    extern __shared__ char sm[];
    int tid = threadIdx.x, l = tid & 31, w = tid >> 5;
    int m0 = blockIdx.x*128;
    int tg = blockIdx.y, t0 = tg*4;
    float c[16][4];
    #pragma unroll
    for (int i = 0; i < 16; i++){ c[i][0]=0.f; c[i][1]=0.f; c[i][2]=0.f; c[i][3]=0.f; }
    gemm_bulk<128,128,128,3>(g_FP + (size_t)blockIdx.x*(32*128*64),
                             d_FBP + (size_t)tg*(32*128*64), sm, c);
    int validT = (tg == 9) ? 3 : 4;
    int t4 = l >> 2, cb = (l & 3)*2;
    #pragma unroll
    for (int nt = 0; nt < 16; nt++){
        int col = nt*8 + cb;
        int tl = col >> 5, b = col & 31;
        if (tl >= validT) continue;
        int tt = t0 + tl;
        #pragma unroll
        for (int p = 0; p < 2; p++){
            int v = m0 + w*16 + t4 + p*8;
            if (v < SV){
                float bias = linb[v];
                size_t o = (size_t)b*((size_t)ST*SV) + (size_t)tt*SV + v;
                out[o] = c[nt][2*p] + bias;
                out[o + (size_t)ST*SV] = c[nt][2*p+1] + bias;
            }
        }
    }
}

// ---------------- launch ----------------
extern "C" void kernel_launch(void* const* d_in, const int* in_sizes, int n_in,
                              void* d_out, int out_size){
    const float* features = (const float*)d_in[0];
    const int*   captions = (const int*)  d_in[1];
    const float* emb      = (const float*)d_in[2];
    const float* lWih     = (const float*)d_in[3];
    const float* lbih     = (const float*)d_in[4];
    const float* lWhh     = (const float*)d_in[5];
    const float* lbhh     = (const float*)d_in[6];
    const float* gWih     = (const float*)d_in[7];
    const float* gbih     = (const float*)d_in[8];
    const float* gWhh     = (const float*)d_in[9];
    const float* gbhh     = (const float*)d_in[10];
    const float* linW     = (const float*)d_in[11];
    const float* linb     = (const float*)d_in[12];
    float* out = (float*)d_out;

    cudaFuncSetAttribute(mmaA_kernel, cudaFuncAttributeMaxDynamicSharedMemorySize, SMEM_STEP);
    cudaFuncSetAttribute(mmaB_kernel, cudaFuncAttributeMaxDynamicSharedMemorySize, SMEM_STEPB);
    cudaFuncSetAttribute(mmaF_kernel, cudaFuncAttributeMaxDynamicSharedMemorySize, SMEM_FIN);

    __half *pL, *pH, *pI, *pF;
    cudaGetSymbolAddress((void**)&pL, g_LP);
    cudaGetSymbolAddress((void**)&pH, g_HP);
    cudaGetSymbolAddress((void**)&pI, g_IP);
    cudaGetSymbolAddress((void**)&pF, g_FP);

    setup_kernel<<<256, 256>>>(features);
    packw_kernel<<<8192, 256>>>(lWhh, pL, 1, 128);
    packw_kernel<<<6144, 256>>>(gWhh, pH, 0, 128);
    packw_kernel<<<6144, 256>>>(gWih, pI, 2, 96);
    packw_kernel<<<8000, 256>>>(linW, pF, 0, 128);
    xg_kernel<<<dim3(ST, 8), 256>>>(captions, emb, lWih, lbih, lbhh);

    for (int t = 0; t < ST; t++){
        mmaA_kernel<<<112, 256, SMEM_STEP>>>(t);
        mmaB_kernel<<<64, 192, SMEM_STEPB>>>(gbih, gbhh, t);
    }
    mmaF_kernel<<<dim3(63, 10), 256, SMEM_FIN>>>(linb, out);
}